// round 14
// baseline (speedup 1.0000x reference)
#include <cuda_runtime.h>
#include <cstdint>
#include <math.h>

#define BATCH 8
#define NA 131072            // anchors per batch (2^17)
#define NPRE 6000            // PRE_NMS_LIMIT
#define NPROP 1000
#define CAND_FAST 4096       // fast-path candidate cap (>= N1 + max bin 2048)
#define CAND_FB 8192         // fallback candidate cap
#define HBINS 16384          // key >> 18
#define NMS_THR 0.7f
#define N1 1536              // fast-path prefix rows
#define ECAP 6144            // edge list capacity per batch
#define PASSMAX 64

typedef unsigned long long u64;

// ---------------- device scratch (static, no allocation) ----------------
// Invariants: g_hist all-zero, g_cand_cnt/g_ecnt zero at entry of each launch
// (zero-init at load; each consumer kernel re-zeroes after use).
__device__ unsigned int  g_hist[BATCH * HBINS];
__device__ int           g_cutbin[BATCH];        // suffix >= N1 cut (fast)
__device__ int           g_cutbin6[BATCH];       // suffix >= NPRE cut (fallback)
__device__ int           g_cand_cnt[BATCH];
__device__ u64           g_cand[BATCH * CAND_FAST];
__device__ float4        g_boxes[BATCH * NPRE];
__device__ int           g_ecnt[BATCH];
__device__ unsigned int  g_edges[BATCH * ECAP];
__device__ int           g_done[BATCH];

// ---------------- helpers ----------------
static __device__ __forceinline__ unsigned int score_key(float s) {
    unsigned int u = __float_as_uint(s);
    return u ^ ((unsigned int)((int)u >> 31) | 0x80000000u);
}
static __device__ __forceinline__ int warp_alloc(bool pred, int* ctr) {
    unsigned int m = __ballot_sync(0xffffffffu, pred);
    int lane = threadIdx.x & 31;
    int leader = __ffs(m) - 1;
    int base = 0;
    if (m) {
        if (lane == leader) base = atomicAdd(ctr, __popc(m));
        base = __shfl_sync(0xffffffffu, base, leader);
    }
    return base + __popc(m & ((1u << lane) - 1u));
}
// merge-path partition (DESC order): of first d outputs, how many come from A
static __device__ __forceinline__ int mpath(const u64* A, int lenA,
                                            const u64* B, int lenB, int d) {
    int lo = d - lenB; if (lo < 0) lo = 0;
    int hi = d < lenA ? d : lenA;
    while (lo < hi) {
        int mid = (lo + hi) >> 1;
        if (A[mid] > B[d - 1 - mid]) lo = mid + 1; else hi = mid;
    }
    return lo;
}
static __device__ __forceinline__ void merge_chunk(const u64* A, int lenA,
                                                   const u64* B, int lenB,
                                                   u64* out, int d) {
    int a = mpath(A, lenA, B, lenB, d);
    int bi = d - a;
#pragma unroll
    for (int r = 0; r < 8; ++r) {
        bool takeA = (a < lenA) && ((bi >= lenB) || (A[a] > B[bi]));
        out[d + r] = takeA ? A[a++] : B[bi++];
    }
}
static __device__ __forceinline__ void decode_box(int b, int rank, u64 v,
                                                  const float* __restrict__ bbox,
                                                  const float* __restrict__ anchors) {
    unsigned int a = ~(unsigned int)(v & 0xffffffffULL);
    size_t s4 = (((size_t)b << 17) + a) * 4;
    float d0 = bbox[s4 + 0] * 0.1f;
    float d1 = bbox[s4 + 1] * 0.1f;
    float d2 = bbox[s4 + 2] * 0.2f;
    float d3 = bbox[s4 + 3] * 0.2f;
    float a0 = anchors[s4 + 0], a1 = anchors[s4 + 1];
    float a2 = anchors[s4 + 2], a3 = anchors[s4 + 3];
    float h = a2 - a0, w = a3 - a1;
    float cy = a0 + 0.5f * h + d0 * h;
    float cx = a1 + 0.5f * w + d1 * w;
    float h2 = h * expf(d2);
    float w2 = w * expf(d3);
    float y1 = cy - 0.5f * h2;
    float x1 = cx - 0.5f * w2;
    float y2 = y1 + h2;
    float x2 = x1 + w2;
    y1 = fminf(fmaxf(y1, 0.f), 1.f);
    x1 = fminf(fmaxf(x1, 0.f), 1.f);
    y2 = fminf(fmaxf(y2, 0.f), 1.f);
    x2 = fminf(fmaxf(x2, 0.f), 1.f);
    g_boxes[b * NPRE + rank] = make_float4(y1, x1, y2, x2);
}

// ---------------- 1: histogram ----------------
__global__ void hist_kernel(const float* __restrict__ probs) {
    const float4* p4 = (const float4*)probs;
    int t = threadIdx.x;
    int base = blockIdx.x * 1024;
    int b = base >> 16;
    float4 x[4];
#pragma unroll
    for (int u = 0; u < 4; ++u) x[u] = p4[base + u * 256 + t];
    unsigned int* Hb = g_hist + (size_t)b * HBINS;
#pragma unroll
    for (int u = 0; u < 4; ++u) {
        atomicAdd(&Hb[score_key(x[u].y) >> 18], 1u);
        atomicAdd(&Hb[score_key(x[u].w) >> 18], 1u);
    }
}

// ---------------- 2: dual cutoff bins (self-cleaning hist) ----------------
__global__ void cutoff_kernel() {
    int b = blockIdx.x, t = threadIdx.x;            // 1024 threads, 16 bins each
    __shared__ unsigned int wtot[32];
    __shared__ unsigned int wsuf[32];
    uint4* H4 = (uint4*)(g_hist + (size_t)b * HBINS);
    int warp = t >> 5, lane = t & 31;
    uint4 h[4];
#pragma unroll
    for (int u = 0; u < 4; ++u) h[u] = H4[t * 4 + u];
    uint4 z = make_uint4(0u, 0u, 0u, 0u);
#pragma unroll
    for (int u = 0; u < 4; ++u) H4[t * 4 + u] = z;  // restore all-zero invariant
    unsigned int s = 0;
#pragma unroll
    for (int u = 0; u < 4; ++u) s += h[u].x + h[u].y + h[u].z + h[u].w;
    unsigned int ss = s;
#pragma unroll
    for (int o = 1; o < 32; o <<= 1) {
        unsigned int v = __shfl_down_sync(0xffffffffu, ss, o);
        if (lane + o < 32) ss += v;
    }
    if (lane == 0) wtot[warp] = ss;
    __syncthreads();
    if (warp == 0) {
        unsigned int wv = wtot[lane];
#pragma unroll
        for (int o = 1; o < 32; o <<= 1) {
            unsigned int v = __shfl_down_sync(0xffffffffu, wv, o);
            if (lane + o < 32) wv += v;
        }
        wsuf[lane] = wv;
    }
    __syncthreads();
    unsigned int after_warp = (warp < 31) ? wsuf[warp + 1] : 0u;
    unsigned int S = ss + after_warp;               // suffix from bin t*16
    unsigned int Snext = S - s;                     // suffix from bin (t+1)*16
    unsigned int bins[16];
#pragma unroll
    for (int u = 0; u < 4; ++u) {
        bins[u * 4 + 0] = h[u].x; bins[u * 4 + 1] = h[u].y;
        bins[u * 4 + 2] = h[u].z; bins[u * 4 + 3] = h[u].w;
    }
    if (S >= N1 && Snext < N1) {                    // fast cut (>= top-1536)
        unsigned int run = Snext;
        int cut = t * 16;
        for (int k = 15; k >= 0; --k) {
            run += bins[k];
            if (run >= N1) { cut = t * 16 + k; break; }
        }
        g_cutbin[b] = cut;
    }
    if (S >= NPRE && Snext < NPRE) {                // fallback cut (>= top-6000)
        unsigned int run = Snext;
        int cut = t * 16;
        for (int k = 15; k >= 0; --k) {
            run += bins[k];
            if (run >= NPRE) { cut = t * 16 + k; break; }
        }
        g_cutbin6[b] = cut;
    }
}

// ---------------- 3: compact fast candidates (cap CAND_FAST) ----------------
__global__ void compact_kernel(const float* __restrict__ probs) {
    const float4* p4 = (const float4*)probs;
    int t = threadIdx.x;
    int base = blockIdx.x * 1024;
    int b = base >> 16;
    int cut = g_cutbin[b];
    float4 x[4];
#pragma unroll
    for (int u = 0; u < 4; ++u) x[u] = p4[base + u * 256 + t];
#pragma unroll
    for (int u = 0; u < 4; ++u) {
        int j = base + u * 256 + t;
        unsigned int k0 = score_key(x[u].y);
        unsigned int k1 = score_key(x[u].w);
        bool p0 = (int)(k0 >> 18) >= cut;
        bool p1 = (int)(k1 >> 18) >= cut;
        int pos0 = warp_alloc(p0, &g_cand_cnt[b]);
        if (p0 && pos0 < CAND_FAST) {
            unsigned int a = (unsigned int)((2 * j) & (NA - 1));
            g_cand[b * CAND_FAST + pos0] = ((u64)k0 << 32) | (u64)(~a);
        }
        int pos1 = warp_alloc(p1, &g_cand_cnt[b]);
        if (p1 && pos1 < CAND_FAST) {
            unsigned int a = (unsigned int)((2 * j + 1) & (NA - 1));
            g_cand[b * CAND_FAST + pos1] = ((u64)k1 << 32) | (u64)(~a);
        }
    }
}

// ---------------- warp-synchronous bitonic (8 elems/lane, i = lane*8 + r) ----------------
static __device__ __forceinline__ void shfl_stage(u64 v[8], int lane, int j, int k) {
    int jm = j >> 3;
#pragma unroll
    for (int r = 0; r < 8; ++r) {
        u64 other = __shfl_xor_sync(0xffffffffu, v[r], jm);
        int i = lane * 8 + r;
        bool lower = (lane & jm) == 0;
        bool desc = ((i & k) == 0);
        bool take_max = (lower == desc);
        u64 mx = v[r] > other ? v[r] : other;
        u64 mn = v[r] > other ? other : v[r];
        v[r] = take_max ? mx : mn;
    }
}
static __device__ __forceinline__ void reg_stage(u64 v[8], int lane, int j, int k) {
#pragma unroll
    for (int a = 0; a < 8; ++a) {
        if (!(a & j)) {
            int i = lane * 8 + a;
            bool desc = ((i & k) == 0);
            u64 x = v[a], y = v[a + j];
            if (desc ? (x < y) : (x > y)) { v[a] = y; v[a + j] = x; }
        }
    }
}
static __device__ __forceinline__ void warp_sort256(u64 v[8], int lane) {
    for (int k = 2; k <= 256; k <<= 1) {
        for (int j = k >> 1; j >= 8; j >>= 1) shfl_stage(v, lane, j, k);
        if (k > 4) reg_stage(v, lane, 4, k);
        if (k > 2) reg_stage(v, lane, 2, k);
        reg_stage(v, lane, 1, k);
    }
}

// ---------------- 4: fused sort(4096) -> top-N1 merge -> decode (8 blocks, 512 thr) ----------------
__global__ void sorttop_kernel(const float* __restrict__ bbox,
                               const float* __restrict__ anchors) {
    extern __shared__ u64 dsm[];                    // S[4096] + P[4096] = 64 KB
    u64* S = dsm;
    u64* P = dsm + CAND_FAST;
    int b = blockIdx.x, t = threadIdx.x;            // 512 threads = 16 warps
    int lane = t & 31, warp = t >> 5;
    int cnt = g_cand_cnt[b];
    int cw = cnt > CAND_FAST ? CAND_FAST : cnt;
    const u64* cand = g_cand + b * CAND_FAST;
    // 16 warps, 1 run each (16 runs of 256), register bitonic, no block sync
    {
        u64 v[8];
        int segbase = warp * 256;
#pragma unroll
        for (int r = 0; r < 8; ++r) {
            int i = segbase + lane * 8 + r;
            v[r] = (i < cw) ? cand[i] : 0ULL;
        }
        warp_sort256(v, lane);
#pragma unroll
        for (int r = 0; r < 8; ++r) S[segbase + lane * 8 + r] = v[r];
    }
    __syncthreads();
    // L1: 8 x (256,256) -> 512 ; 512 chunks, 1 per thread
    {
        int m = t >> 6, d = (t & 63) * 8;
        merge_chunk(S + 2 * m * 256, 256, S + 2 * m * 256 + 256, 256,
                    P + m * 512, d);
    }
    __syncthreads();
    // L2: 4 x (512,512) -> 1024
    {
        int m = t >> 7, d = (t & 127) * 8;
        merge_chunk(P + 2 * m * 512, 512, P + 2 * m * 512 + 512, 512,
                    S + m * 1024, d);
    }
    __syncthreads();
    // L3: 2 x (1024,1024) -> 2048
    {
        int m = t >> 8, d = (t & 255) * 8;
        merge_chunk(S + 2 * m * 1024, 1024, S + 2 * m * 1024 + 1024, 1024,
                    P + m * 2048, d);
    }
    __syncthreads();
    // L4: (2048,2048) -> top N1 ; 192 chunks
    if (t < N1 / 8)
        merge_chunk(P, 2048, P + 2048, 2048, S, t * 8);
    __syncthreads();
    for (int rank = t; rank < N1; rank += 512)
        decode_box(b, rank, S[rank], bbox, anchors);
}

// ---------------- 5: edge emission over first N1 boxes ----------------
__global__ void edge_kernel() {
    int rowblk = blockIdx.x, colblk = blockIdx.y, b = blockIdx.z;
    if (colblk < 2 * rowblk) return;
    int t = threadIdx.x;
    int i0 = rowblk * 128 + t;
    int i1 = i0 + 64;
    __shared__ float4 s_box[64];
    __shared__ float  s_area[64];
    int jj0 = colblk * 64;
    const float4* boxes_b = g_boxes + b * NPRE;
    {
        float4 c = boxes_b[jj0 + t];
        s_box[t] = c;
        s_area[t] = (c.z - c.x) * (c.w - c.y);
    }
    __syncthreads();
    float4 rb0 = boxes_b[i0];
    float4 rb1 = boxes_b[i1];
    float ar0 = (rb0.z - rb0.x) * (rb0.w - rb0.y);
    float ar1 = (rb1.z - rb1.x) * (rb1.w - rb1.y);
#pragma unroll 4
    for (int j = 0; j < 64; ++j) {
        float4 c = s_box[j];
        float ca = s_area[j];
        int jj = jj0 + j;
        float dy0 = fminf(rb0.z, c.z) - fmaxf(rb0.x, c.x);
        float dx0 = fminf(rb0.w, c.w) - fmaxf(rb0.y, c.y);
        float dy1 = fminf(rb1.z, c.z) - fmaxf(rb1.x, c.x);
        float dx1 = fminf(rb1.w, c.w) - fmaxf(rb1.y, c.y);
        bool ov0 = (dy0 > 0.f) && (dx0 > 0.f) && (jj > i0);
        bool ov1 = (dy1 > 0.f) && (dx1 > 0.f) && (jj > i1);
        if (__any_sync(0xffffffffu, ov0 || ov1)) {
            bool e0 = false, e1 = false;
            if (ov0) {
                float inter = dy0 * dx0;
                float uni = fmaxf(ar0 + ca - inter, 1e-12f);
                e0 = __fdiv_rn(inter, uni) > NMS_THR;
            }
            if (ov1) {
                float inter = dy1 * dx1;
                float uni = fmaxf(ar1 + ca - inter, 1e-12f);
                e1 = __fdiv_rn(inter, uni) > NMS_THR;
            }
            int pos0 = warp_alloc(e0, &g_ecnt[b]);
            if (e0 && pos0 < ECAP)
                g_edges[b * ECAP + pos0] = ((unsigned int)i0 << 16) | (unsigned int)jj;
            int pos1 = warp_alloc(e1, &g_ecnt[b]);
            if (e1 && pos1 < ECAP)
                g_edges[b * ECAP + pos1] = ((unsigned int)i1 << 16) | (unsigned int)jj;
        }
    }
}

// ---------------- 6: fixpoint NMS on prefix + fused output write ----------------
__global__ void fixpoint_out_kernel(float* __restrict__ out) {
    int b = blockIdx.x, t = threadIdx.x;            // 256 threads
    int warp = t >> 5, lane = t & 31;
    __shared__ unsigned int  s_edges[ECAP];
    __shared__ unsigned char s_keep[N1];
    __shared__ unsigned char s_supp[N1];
    __shared__ int s_flag, s_total, s_base;
    __shared__ int s_w[8];
    int ec = g_ecnt[b];
    int cc = g_cand_cnt[b];
    if (t == 0) { g_ecnt[b] = 0; g_cand_cnt[b] = 0; }   // restore invariants
    if (ec > ECAP || cc > CAND_FAST) {                  // overflow -> exact fallback
        if (t == 0) g_done[b] = 0;
        return;
    }
    for (int i = t; i < ec; i += 256) s_edges[i] = g_edges[b * ECAP + i];
    for (int i = t; i < N1; i += 256) s_keep[i] = 1;
    __syncthreads();
    bool converged = false;
    for (int pass = 0; pass < PASSMAX; ++pass) {
        for (int i = t; i < N1; i += 256) s_supp[i] = 0;
        if (t == 0) s_flag = 0;
        __syncthreads();
        for (int e = t; e < ec; e += 256) {
            unsigned int p = s_edges[e];
            if (s_keep[p >> 16]) s_supp[p & 0xffffu] = 1;
        }
        __syncthreads();
        int ch = 0;
        for (int i = t; i < N1; i += 256) {
            unsigned char nk = (unsigned char)(1 - s_supp[i]);
            if (nk != s_keep[i]) { s_keep[i] = nk; ch = 1; }
        }
        if (ch) s_flag = 1;
        __syncthreads();
        if (!s_flag) { converged = true; break; }
    }
    if (t == 0) s_total = 0;
    __syncthreads();
    int cnt = 0;
    for (int i = t; i < N1; i += 256) cnt += s_keep[i];
    for (int off = 16; off > 0; off >>= 1) cnt += __shfl_down_sync(0xffffffffu, cnt, off);
    if (lane == 0) atomicAdd(&s_total, cnt);
    __syncthreads();
    int done = (converged && s_total >= NPROP) ? 1 : 0;
    if (t == 0) { g_done[b] = done; s_base = 0; }
    __syncthreads();
    if (!done) return;                              // fallback kernel writes output
    for (int k = t; k < NPROP * 4; k += 256) out[b * NPROP * 4 + k] = 0.f;
    __syncthreads();
    for (int tile = 0; tile < N1 / 256; ++tile) {
        int i = tile * 256 + t;
        int kp = (int)s_keep[i];
        unsigned int m = __ballot_sync(0xffffffffu, kp);
        if (lane == 0) s_w[warp] = __popc(m);
        __syncthreads();
        int base = s_base;
        if (warp == 0 && lane < 8) {
            int wv = s_w[lane];
            for (int o = 1; o < 8; o <<= 1) {
                int u = __shfl_up_sync(0xffu, wv, o);
                if (lane >= o) wv += u;
            }
            s_w[lane] = wv;                          // inclusive
        }
        __syncthreads();
        int prev = (warp == 0) ? 0 : s_w[warp - 1];
        int rank = base + prev + __popc(m & ((1u << lane) - 1u));
        if (kp && rank < NPROP)
            ((float4*)out)[b * NPROP + rank] = g_boxes[b * NPRE + i];
        __syncthreads();
        if (t == 0) s_base = base + s_w[7];
        __syncthreads();
    }
}

// ---------------- 7: FALLBACK all-in-one (guarded; ~never runs) ----------------
// Per batch: re-select with cutB -> full smem sort -> top-6000 decode ->
// sequential greedy NMS -> compact. Exact reference semantics.
__global__ void fallback_kernel(const float* __restrict__ probs,
                                const float* __restrict__ bbox,
                                const float* __restrict__ anchors,
                                float* __restrict__ out) {
    int b = blockIdx.x, t = threadIdx.x;            // 256 threads
    if (g_done[b]) return;
    extern __shared__ u64 fsm[];                    // A[8192] + B[8192] + supp + cnt
    u64* A = fsm;
    u64* B = fsm + CAND_FB;
    unsigned char* supp = (unsigned char*)(fsm + 2 * CAND_FB);
    int* s_cnt = (int*)(supp + NPRE + (8 - (NPRE & 7)));
    int warp = t >> 5, lane = t & 31;
    __shared__ int s_w[8];
    __shared__ int s_base;
    for (int i = t; i < CAND_FB; i += 256) A[i] = 0ULL;
    if (t == 0) *s_cnt = 0;
    __syncthreads();
    {
        int cut = g_cutbin6[b];
        const float4* p4 = (const float4*)probs + ((size_t)b << 16);
        for (int i = t; i < (NA / 2); i += 256) {
            float4 x = p4[i];
            unsigned int k0 = score_key(x.y);
            unsigned int k1 = score_key(x.w);
            bool p0 = (int)(k0 >> 18) >= cut;
            bool p1 = (int)(k1 >> 18) >= cut;
            int pos0 = warp_alloc(p0, s_cnt);
            if (p0 && pos0 < CAND_FB)
                A[pos0] = ((u64)k0 << 32) | (u64)(~(unsigned int)(2 * i));
            int pos1 = warp_alloc(p1, s_cnt);
            if (p1 && pos1 < CAND_FB)
                A[pos1] = ((u64)k1 << 32) | (u64)(~(unsigned int)(2 * i + 1));
        }
    }
    __syncthreads();
    for (int run = warp; run < 32; run += 8) {
        u64 v[8];
#pragma unroll
        for (int r = 0; r < 8; ++r) v[r] = A[run * 256 + lane * 8 + r];
        warp_sort256(v, lane);
#pragma unroll
        for (int r = 0; r < 8; ++r) A[run * 256 + lane * 8 + r] = v[r];
    }
    __syncthreads();
    for (int c = t; c < 1024; c += 256) {           // L1 -> B
        int m = c >> 6, d = (c & 63) * 8;
        merge_chunk(A + 2 * m * 256, 256, A + 2 * m * 256 + 256, 256, B + m * 512, d);
    }
    __syncthreads();
    for (int c = t; c < 1024; c += 256) {           // L2 -> A
        int m = c >> 7, d = (c & 127) * 8;
        merge_chunk(B + 2 * m * 512, 512, B + 2 * m * 512 + 512, 512, A + m * 1024, d);
    }
    __syncthreads();
    for (int c = t; c < 1024; c += 256) {           // L3 -> B
        int m = c >> 8, d = (c & 255) * 8;
        merge_chunk(A + 2 * m * 1024, 1024, A + 2 * m * 1024 + 1024, 1024,
                    B + m * 2048, d);
    }
    __syncthreads();
    for (int c = t; c < 1024; c += 256) {           // L4 -> A
        int m = c >> 9, d = (c & 511) * 8;
        merge_chunk(B + 2 * m * 2048, 2048, B + 2 * m * 2048 + 2048, 2048,
                    A + m * 4096, d);
    }
    __syncthreads();
    for (int c = t; c < NPRE / 8; c += 256)         // L5 -> B (top 6000)
        merge_chunk(A, 4096, A + 4096, 4096, B, c * 8);
    __syncthreads();
    for (int rank = t; rank < NPRE; rank += 256)
        decode_box(b, rank, B[rank], bbox, anchors);
    for (int i = t; i < NPRE; i += 256) supp[i] = 0;
    __syncthreads();
    const float4* boxes_b = g_boxes + b * NPRE;
    for (int i = 0; i < NPRE; ++i) {
        if (!supp[i]) {
            float4 bi_ = boxes_b[i];
            float ai = (bi_.z - bi_.x) * (bi_.w - bi_.y);
            for (int j = i + 1 + t; j < NPRE; j += 256) {
                if (supp[j]) continue;
                float4 c = boxes_b[j];
                float dy = fminf(bi_.z, c.z) - fmaxf(bi_.x, c.x);
                float dx = fminf(bi_.w, c.w) - fmaxf(bi_.y, c.y);
                if (dy > 0.f && dx > 0.f) {
                    float inter = dy * dx;
                    float ca = (c.z - c.x) * (c.w - c.y);
                    float uni = fmaxf(ai + ca - inter, 1e-12f);
                    if (__fdiv_rn(inter, uni) > NMS_THR) supp[j] = 1;
                }
            }
        }
        __syncthreads();
    }
    for (int k = t; k < NPROP * 4; k += 256) out[b * NPROP * 4 + k] = 0.f;
    if (t == 0) s_base = 0;
    __syncthreads();
    for (int tile = 0; tile < 24; ++tile) {
        int i = tile * 256 + t;
        int kp = (i < NPRE) ? (int)(1 - supp[i]) : 0;
        unsigned int m = __ballot_sync(0xffffffffu, kp);
        if (lane == 0) s_w[warp] = __popc(m);
        __syncthreads();
        int base = s_base;
        if (warp == 0 && lane < 8) {
            int wv = s_w[lane];
            for (int o = 1; o < 8; o <<= 1) {
                int u = __shfl_up_sync(0xffu, wv, o);
                if (lane >= o) wv += u;
            }
            s_w[lane] = wv;
        }
        __syncthreads();
        int prev = (warp == 0) ? 0 : s_w[warp - 1];
        int rank = base + prev + __popc(m & ((1u << lane) - 1u));
        if (kp && rank < NPROP)
            ((float4*)out)[b * NPROP + rank] = boxes_b[i];
        __syncthreads();
        if (t == 0) s_base = base + s_w[7];
        __syncthreads();
    }
}

// ---------------- launch ----------------
extern "C" void kernel_launch(void* const* d_in, const int* in_sizes, int n_in,
                              void* d_out, int out_size) {
    const float* probs   = (const float*)d_in[0];
    const float* bbox    = (const float*)d_in[1];
    const float* anchors = (const float*)d_in[2];
    float* out = (float*)d_out;

    const int st_smem = 2 * CAND_FAST * 8;                    // 65536 B
    const int fb_smem = 2 * CAND_FB * 8 + NPRE + 64;          // ~137 KB
    cudaFuncSetAttribute(sorttop_kernel,
                         cudaFuncAttributeMaxDynamicSharedMemorySize, st_smem);
    cudaFuncSetAttribute(fallback_kernel,
                         cudaFuncAttributeMaxDynamicSharedMemorySize, fb_smem);

    hist_kernel<<<512, 256>>>(probs);
    cutoff_kernel<<<BATCH, 1024>>>();
    compact_kernel<<<512, 256>>>(probs);
    sorttop_kernel<<<BATCH, 512, st_smem>>>(bbox, anchors);
    edge_kernel<<<dim3(12, 24, BATCH), 64>>>();
    fixpoint_out_kernel<<<BATCH, 256>>>(out);
    fallback_kernel<<<BATCH, 256, fb_smem>>>(probs, bbox, anchors, out);  // no-op when done
}

// round 15
// speedup vs baseline: 1.6253x; 1.6253x over previous
#include <cuda_runtime.h>
#include <cstdint>
#include <math.h>

#define BATCH 8
#define NA 131072            // anchors per batch (2^17)
#define NPRE 6000            // PRE_NMS_LIMIT
#define NPROP 1000
#define CAND_FAST 2048       // fast-path candidate cap (fine bins: ~1536+~350)
#define CAND_FB 8192         // fallback candidate cap
#define HBINS 16384          // fine bins: (key>>15) - BIN_OFF, clamped
#define BIN_OFF 0x13F01      // (0xBF800000>>15) - (HBINS-1): score 1.0 -> bin 16383
#define NMS_THR 0.7f
#define N1 1536              // fast-path prefix rows
#define ECAP 6144            // edge list capacity per batch
#define PASSMAX 64

typedef unsigned long long u64;

// ---------------- device scratch (static, no allocation) ----------------
// Invariants: g_hist all-zero, g_cand_cnt/g_ecnt zero at entry of each launch
// (zero-init at load; each consumer kernel re-zeroes after use).
__device__ unsigned int  g_hist[BATCH * HBINS];
__device__ int           g_cutbin[BATCH];        // suffix >= N1 cut (fast)
__device__ int           g_cutbin6[BATCH];       // suffix >= NPRE cut (fallback)
__device__ int           g_cand_cnt[BATCH];
__device__ u64           g_cand[BATCH * CAND_FAST];
__device__ float4        g_boxes[BATCH * NPRE];
__device__ int           g_ecnt[BATCH];
__device__ unsigned int  g_edges[BATCH * ECAP];
__device__ int           g_done[BATCH];

// ---------------- helpers ----------------
static __device__ __forceinline__ unsigned int score_key(float s) {
    unsigned int u = __float_as_uint(s);
    return u ^ ((unsigned int)((int)u >> 31) | 0x80000000u);
}
static __device__ __forceinline__ int key_bin(unsigned int key) {
    int b = (int)(key >> 15) - BIN_OFF;
    return b < 0 ? 0 : (b > HBINS - 1 ? HBINS - 1 : b);
}
static __device__ __forceinline__ int warp_alloc(bool pred, int* ctr) {
    unsigned int m = __ballot_sync(0xffffffffu, pred);
    int lane = threadIdx.x & 31;
    int leader = __ffs(m) - 1;
    int base = 0;
    if (m) {
        if (lane == leader) base = atomicAdd(ctr, __popc(m));
        base = __shfl_sync(0xffffffffu, base, leader);
    }
    return base + __popc(m & ((1u << lane) - 1u));
}
// merge-path partition (DESC order): of first d outputs, how many come from A
static __device__ __forceinline__ int mpath(const u64* A, int lenA,
                                            const u64* B, int lenB, int d) {
    int lo = d - lenB; if (lo < 0) lo = 0;
    int hi = d < lenA ? d : lenA;
    while (lo < hi) {
        int mid = (lo + hi) >> 1;
        if (A[mid] > B[d - 1 - mid]) lo = mid + 1; else hi = mid;
    }
    return lo;
}
static __device__ __forceinline__ void merge_chunk(const u64* A, int lenA,
                                                   const u64* B, int lenB,
                                                   u64* out, int d) {
    int a = mpath(A, lenA, B, lenB, d);
    int bi = d - a;
#pragma unroll
    for (int r = 0; r < 8; ++r) {
        bool takeA = (a < lenA) && ((bi >= lenB) || (A[a] > B[bi]));
        out[d + r] = takeA ? A[a++] : B[bi++];
    }
}
static __device__ __forceinline__ void decode_box(int b, int rank, u64 v,
                                                  const float* __restrict__ bbox,
                                                  const float* __restrict__ anchors) {
    unsigned int a = ~(unsigned int)(v & 0xffffffffULL);
    size_t s4 = (((size_t)b << 17) + a) * 4;
    float d0 = bbox[s4 + 0] * 0.1f;
    float d1 = bbox[s4 + 1] * 0.1f;
    float d2 = bbox[s4 + 2] * 0.2f;
    float d3 = bbox[s4 + 3] * 0.2f;
    float a0 = anchors[s4 + 0], a1 = anchors[s4 + 1];
    float a2 = anchors[s4 + 2], a3 = anchors[s4 + 3];
    float h = a2 - a0, w = a3 - a1;
    float cy = a0 + 0.5f * h + d0 * h;
    float cx = a1 + 0.5f * w + d1 * w;
    float h2 = h * expf(d2);
    float w2 = w * expf(d3);
    float y1 = cy - 0.5f * h2;
    float x1 = cx - 0.5f * w2;
    float y2 = y1 + h2;
    float x2 = x1 + w2;
    y1 = fminf(fmaxf(y1, 0.f), 1.f);
    x1 = fminf(fmaxf(x1, 0.f), 1.f);
    y2 = fminf(fmaxf(y2, 0.f), 1.f);
    x2 = fminf(fmaxf(x2, 0.f), 1.f);
    g_boxes[b * NPRE + rank] = make_float4(y1, x1, y2, x2);
}

// ---------------- 1: histogram ----------------
__global__ void hist_kernel(const float* __restrict__ probs) {
    const float4* p4 = (const float4*)probs;
    int t = threadIdx.x;
    int base = blockIdx.x * 1024;
    int b = base >> 16;
    float4 x[4];
#pragma unroll
    for (int u = 0; u < 4; ++u) x[u] = p4[base + u * 256 + t];
    unsigned int* Hb = g_hist + (size_t)b * HBINS;
#pragma unroll
    for (int u = 0; u < 4; ++u) {
        atomicAdd(&Hb[key_bin(score_key(x[u].y))], 1u);
        atomicAdd(&Hb[key_bin(score_key(x[u].w))], 1u);
    }
}

// ---------------- 2: dual cutoff bins (self-cleaning hist) ----------------
__global__ void cutoff_kernel() {
    int b = blockIdx.x, t = threadIdx.x;            // 1024 threads, 16 bins each
    __shared__ unsigned int wtot[32];
    __shared__ unsigned int wsuf[32];
    uint4* H4 = (uint4*)(g_hist + (size_t)b * HBINS);
    int warp = t >> 5, lane = t & 31;
    uint4 h[4];
#pragma unroll
    for (int u = 0; u < 4; ++u) h[u] = H4[t * 4 + u];
    uint4 z = make_uint4(0u, 0u, 0u, 0u);
#pragma unroll
    for (int u = 0; u < 4; ++u) H4[t * 4 + u] = z;  // restore all-zero invariant
    unsigned int s = 0;
#pragma unroll
    for (int u = 0; u < 4; ++u) s += h[u].x + h[u].y + h[u].z + h[u].w;
    unsigned int ss = s;
#pragma unroll
    for (int o = 1; o < 32; o <<= 1) {
        unsigned int v = __shfl_down_sync(0xffffffffu, ss, o);
        if (lane + o < 32) ss += v;
    }
    if (lane == 0) wtot[warp] = ss;
    __syncthreads();
    if (warp == 0) {
        unsigned int wv = wtot[lane];
#pragma unroll
        for (int o = 1; o < 32; o <<= 1) {
            unsigned int v = __shfl_down_sync(0xffffffffu, wv, o);
            if (lane + o < 32) wv += v;
        }
        wsuf[lane] = wv;
    }
    __syncthreads();
    unsigned int after_warp = (warp < 31) ? wsuf[warp + 1] : 0u;
    unsigned int S = ss + after_warp;               // suffix from bin t*16
    unsigned int Snext = S - s;                     // suffix from bin (t+1)*16
    unsigned int bins[16];
#pragma unroll
    for (int u = 0; u < 4; ++u) {
        bins[u * 4 + 0] = h[u].x; bins[u * 4 + 1] = h[u].y;
        bins[u * 4 + 2] = h[u].z; bins[u * 4 + 3] = h[u].w;
    }
    if (S >= N1 && Snext < N1) {                    // fast cut (>= top-1536)
        unsigned int run = Snext;
        int cut = t * 16;
        for (int k = 15; k >= 0; --k) {
            run += bins[k];
            if (run >= N1) { cut = t * 16 + k; break; }
        }
        g_cutbin[b] = cut;
    }
    if (S >= NPRE && Snext < NPRE) {                // fallback cut (>= top-6000)
        unsigned int run = Snext;
        int cut = t * 16;
        for (int k = 15; k >= 0; --k) {
            run += bins[k];
            if (run >= NPRE) { cut = t * 16 + k; break; }
        }
        g_cutbin6[b] = cut;
    }
}

// ---------------- 3: compact fast candidates (cap CAND_FAST) ----------------
__global__ void compact_kernel(const float* __restrict__ probs) {
    const float4* p4 = (const float4*)probs;
    int t = threadIdx.x;
    int base = blockIdx.x * 1024;
    int b = base >> 16;
    int cut = g_cutbin[b];
    float4 x[4];
#pragma unroll
    for (int u = 0; u < 4; ++u) x[u] = p4[base + u * 256 + t];
#pragma unroll
    for (int u = 0; u < 4; ++u) {
        int j = base + u * 256 + t;
        unsigned int k0 = score_key(x[u].y);
        unsigned int k1 = score_key(x[u].w);
        bool p0 = key_bin(k0) >= cut;
        bool p1 = key_bin(k1) >= cut;
        int pos0 = warp_alloc(p0, &g_cand_cnt[b]);
        if (p0 && pos0 < CAND_FAST) {
            unsigned int a = (unsigned int)((2 * j) & (NA - 1));
            g_cand[b * CAND_FAST + pos0] = ((u64)k0 << 32) | (u64)(~a);
        }
        int pos1 = warp_alloc(p1, &g_cand_cnt[b]);
        if (p1 && pos1 < CAND_FAST) {
            unsigned int a = (unsigned int)((2 * j + 1) & (NA - 1));
            g_cand[b * CAND_FAST + pos1] = ((u64)k1 << 32) | (u64)(~a);
        }
    }
}

// ---------------- warp-synchronous bitonic (8 elems/lane, i = lane*8 + r) ----------------
static __device__ __forceinline__ void shfl_stage(u64 v[8], int lane, int j, int k) {
    int jm = j >> 3;
#pragma unroll
    for (int r = 0; r < 8; ++r) {
        u64 other = __shfl_xor_sync(0xffffffffu, v[r], jm);
        int i = lane * 8 + r;
        bool lower = (lane & jm) == 0;
        bool desc = ((i & k) == 0);
        bool take_max = (lower == desc);
        u64 mx = v[r] > other ? v[r] : other;
        u64 mn = v[r] > other ? other : v[r];
        v[r] = take_max ? mx : mn;
    }
}
static __device__ __forceinline__ void reg_stage(u64 v[8], int lane, int j, int k) {
#pragma unroll
    for (int a = 0; a < 8; ++a) {
        if (!(a & j)) {
            int i = lane * 8 + a;
            bool desc = ((i & k) == 0);
            u64 x = v[a], y = v[a + j];
            if (desc ? (x < y) : (x > y)) { v[a] = y; v[a + j] = x; }
        }
    }
}
static __device__ __forceinline__ void warp_sort256(u64 v[8], int lane) {
    for (int k = 2; k <= 256; k <<= 1) {
        for (int j = k >> 1; j >= 8; j >>= 1) shfl_stage(v, lane, j, k);
        if (k > 4) reg_stage(v, lane, 4, k);
        if (k > 2) reg_stage(v, lane, 2, k);
        reg_stage(v, lane, 1, k);
    }
}

// ---------------- 4: fused sort(2048) -> top-N1 merge -> decode (8 blocks, 256 thr) ----------------
__global__ void sorttop_kernel(const float* __restrict__ bbox,
                               const float* __restrict__ anchors) {
    __shared__ u64 S[CAND_FAST];
    __shared__ u64 P[CAND_FAST];
    int b = blockIdx.x, t = threadIdx.x;            // 256 threads = 8 warps
    int lane = t & 31, warp = t >> 5;
    int cnt = g_cand_cnt[b];
    int cw = cnt > CAND_FAST ? CAND_FAST : cnt;
    const u64* cand = g_cand + b * CAND_FAST;
    // 8 warps, 1 run each (8 runs of 256), register bitonic, no block sync
    {
        u64 v[8];
        int segbase = warp * 256;
#pragma unroll
        for (int r = 0; r < 8; ++r) {
            int i = segbase + lane * 8 + r;
            v[r] = (i < cw) ? cand[i] : 0ULL;
        }
        warp_sort256(v, lane);
#pragma unroll
        for (int r = 0; r < 8; ++r) S[segbase + lane * 8 + r] = v[r];
    }
    __syncthreads();
    // L1: 4 x (256,256) -> 512 ; 256 chunks, 1 per thread
    {
        int m = t >> 6, d = (t & 63) * 8;
        merge_chunk(S + 2 * m * 256, 256, S + 2 * m * 256 + 256, 256,
                    P + m * 512, d);
    }
    __syncthreads();
    // L2: 2 x (512,512) -> 1024
    {
        int m = t >> 7, d = (t & 127) * 8;
        merge_chunk(P + 2 * m * 512, 512, P + 2 * m * 512 + 512, 512,
                    S + m * 1024, d);
    }
    __syncthreads();
    // L3: (1024,1024) -> top N1 ; 192 chunks
    if (t < N1 / 8)
        merge_chunk(S, 1024, S + 1024, 1024, P, t * 8);
    __syncthreads();
    for (int rank = t; rank < N1; rank += 256)
        decode_box(b, rank, P[rank], bbox, anchors);
}

// ---------------- 5: edge emission over first N1 boxes ----------------
__global__ void edge_kernel() {
    int rowblk = blockIdx.x, colblk = blockIdx.y, b = blockIdx.z;
    if (colblk < 2 * rowblk) return;
    int t = threadIdx.x;
    int i0 = rowblk * 128 + t;
    int i1 = i0 + 64;
    __shared__ float4 s_box[64];
    __shared__ float  s_area[64];
    int jj0 = colblk * 64;
    const float4* boxes_b = g_boxes + b * NPRE;
    {
        float4 c = boxes_b[jj0 + t];
        s_box[t] = c;
        s_area[t] = (c.z - c.x) * (c.w - c.y);
    }
    __syncthreads();
    float4 rb0 = boxes_b[i0];
    float4 rb1 = boxes_b[i1];
    float ar0 = (rb0.z - rb0.x) * (rb0.w - rb0.y);
    float ar1 = (rb1.z - rb1.x) * (rb1.w - rb1.y);
#pragma unroll 4
    for (int j = 0; j < 64; ++j) {
        float4 c = s_box[j];
        float ca = s_area[j];
        int jj = jj0 + j;
        float dy0 = fminf(rb0.z, c.z) - fmaxf(rb0.x, c.x);
        float dx0 = fminf(rb0.w, c.w) - fmaxf(rb0.y, c.y);
        float dy1 = fminf(rb1.z, c.z) - fmaxf(rb1.x, c.x);
        float dx1 = fminf(rb1.w, c.w) - fmaxf(rb1.y, c.y);
        bool ov0 = (dy0 > 0.f) && (dx0 > 0.f) && (jj > i0);
        bool ov1 = (dy1 > 0.f) && (dx1 > 0.f) && (jj > i1);
        if (__any_sync(0xffffffffu, ov0 || ov1)) {
            bool e0 = false, e1 = false;
            if (ov0) {
                float inter = dy0 * dx0;
                float uni = fmaxf(ar0 + ca - inter, 1e-12f);
                e0 = __fdiv_rn(inter, uni) > NMS_THR;
            }
            if (ov1) {
                float inter = dy1 * dx1;
                float uni = fmaxf(ar1 + ca - inter, 1e-12f);
                e1 = __fdiv_rn(inter, uni) > NMS_THR;
            }
            int pos0 = warp_alloc(e0, &g_ecnt[b]);
            if (e0 && pos0 < ECAP)
                g_edges[b * ECAP + pos0] = ((unsigned int)i0 << 16) | (unsigned int)jj;
            int pos1 = warp_alloc(e1, &g_ecnt[b]);
            if (e1 && pos1 < ECAP)
                g_edges[b * ECAP + pos1] = ((unsigned int)i1 << 16) | (unsigned int)jj;
        }
    }
}

// ---------------- 6: fixpoint NMS on prefix + fused output write ----------------
__global__ void fixpoint_out_kernel(float* __restrict__ out) {
    int b = blockIdx.x, t = threadIdx.x;            // 256 threads
    int warp = t >> 5, lane = t & 31;
    __shared__ unsigned int  s_edges[ECAP];
    __shared__ unsigned char s_keep[N1];
    __shared__ unsigned char s_supp[N1];
    __shared__ int s_flag, s_total, s_base;
    __shared__ int s_w[8];
    int ec = g_ecnt[b];
    int cc = g_cand_cnt[b];
    if (t == 0) { g_ecnt[b] = 0; g_cand_cnt[b] = 0; }   // restore invariants
    if (ec > ECAP || cc > CAND_FAST) {                  // overflow -> exact fallback
        if (t == 0) g_done[b] = 0;
        return;
    }
    for (int i = t; i < ec; i += 256) s_edges[i] = g_edges[b * ECAP + i];
    for (int i = t; i < N1; i += 256) s_keep[i] = 1;
    __syncthreads();
    bool converged = false;
    for (int pass = 0; pass < PASSMAX; ++pass) {
        for (int i = t; i < N1; i += 256) s_supp[i] = 0;
        if (t == 0) s_flag = 0;
        __syncthreads();
        for (int e = t; e < ec; e += 256) {
            unsigned int p = s_edges[e];
            if (s_keep[p >> 16]) s_supp[p & 0xffffu] = 1;
        }
        __syncthreads();
        int ch = 0;
        for (int i = t; i < N1; i += 256) {
            unsigned char nk = (unsigned char)(1 - s_supp[i]);
            if (nk != s_keep[i]) { s_keep[i] = nk; ch = 1; }
        }
        if (ch) s_flag = 1;
        __syncthreads();
        if (!s_flag) { converged = true; break; }
    }
    if (t == 0) s_total = 0;
    __syncthreads();
    int cnt = 0;
    for (int i = t; i < N1; i += 256) cnt += s_keep[i];
    for (int off = 16; off > 0; off >>= 1) cnt += __shfl_down_sync(0xffffffffu, cnt, off);
    if (lane == 0) atomicAdd(&s_total, cnt);
    __syncthreads();
    int done = (converged && s_total >= NPROP) ? 1 : 0;
    if (t == 0) { g_done[b] = done; s_base = 0; }
    __syncthreads();
    if (!done) return;                              // fallback kernel writes output
    for (int k = t; k < NPROP * 4; k += 256) out[b * NPROP * 4 + k] = 0.f;
    __syncthreads();
    for (int tile = 0; tile < N1 / 256; ++tile) {
        int i = tile * 256 + t;
        int kp = (int)s_keep[i];
        unsigned int m = __ballot_sync(0xffffffffu, kp);
        if (lane == 0) s_w[warp] = __popc(m);
        __syncthreads();
        int base = s_base;
        if (warp == 0 && lane < 8) {
            int wv = s_w[lane];
            for (int o = 1; o < 8; o <<= 1) {
                int u = __shfl_up_sync(0xffu, wv, o);
                if (lane >= o) wv += u;
            }
            s_w[lane] = wv;                          // inclusive
        }
        __syncthreads();
        int prev = (warp == 0) ? 0 : s_w[warp - 1];
        int rank = base + prev + __popc(m & ((1u << lane) - 1u));
        if (kp && rank < NPROP)
            ((float4*)out)[b * NPROP + rank] = g_boxes[b * NPRE + i];
        __syncthreads();
        if (t == 0) s_base = base + s_w[7];
        __syncthreads();
    }
}

// ---------------- 7: FALLBACK all-in-one (guarded; ~never runs) ----------------
// Per batch: re-select with cutB -> full smem sort -> top-6000 decode ->
// sequential greedy NMS -> compact. Exact reference semantics.
__global__ void fallback_kernel(const float* __restrict__ probs,
                                const float* __restrict__ bbox,
                                const float* __restrict__ anchors,
                                float* __restrict__ out) {
    int b = blockIdx.x, t = threadIdx.x;            // 256 threads
    if (g_done[b]) return;
    extern __shared__ u64 fsm[];                    // A[8192] + B[8192] + supp + cnt
    u64* A = fsm;
    u64* B = fsm + CAND_FB;
    unsigned char* supp = (unsigned char*)(fsm + 2 * CAND_FB);
    int* s_cnt = (int*)(supp + NPRE + (8 - (NPRE & 7)));
    int warp = t >> 5, lane = t & 31;
    __shared__ int s_w[8];
    __shared__ int s_base;
    for (int i = t; i < CAND_FB; i += 256) A[i] = 0ULL;
    if (t == 0) *s_cnt = 0;
    __syncthreads();
    {
        int cut = g_cutbin6[b];
        const float4* p4 = (const float4*)probs + ((size_t)b << 16);
        for (int i = t; i < (NA / 2); i += 256) {
            float4 x = p4[i];
            unsigned int k0 = score_key(x.y);
            unsigned int k1 = score_key(x.w);
            bool p0 = key_bin(k0) >= cut;
            bool p1 = key_bin(k1) >= cut;
            int pos0 = warp_alloc(p0, s_cnt);
            if (p0 && pos0 < CAND_FB)
                A[pos0] = ((u64)k0 << 32) | (u64)(~(unsigned int)(2 * i));
            int pos1 = warp_alloc(p1, s_cnt);
            if (p1 && pos1 < CAND_FB)
                A[pos1] = ((u64)k1 << 32) | (u64)(~(unsigned int)(2 * i + 1));
        }
    }
    __syncthreads();
    for (int run = warp; run < 32; run += 8) {
        u64 v[8];
#pragma unroll
        for (int r = 0; r < 8; ++r) v[r] = A[run * 256 + lane * 8 + r];
        warp_sort256(v, lane);
#pragma unroll
        for (int r = 0; r < 8; ++r) A[run * 256 + lane * 8 + r] = v[r];
    }
    __syncthreads();
    for (int c = t; c < 1024; c += 256) {           // L1 -> B
        int m = c >> 6, d = (c & 63) * 8;
        merge_chunk(A + 2 * m * 256, 256, A + 2 * m * 256 + 256, 256, B + m * 512, d);
    }
    __syncthreads();
    for (int c = t; c < 1024; c += 256) {           // L2 -> A
        int m = c >> 7, d = (c & 127) * 8;
        merge_chunk(B + 2 * m * 512, 512, B + 2 * m * 512 + 512, 512, A + m * 1024, d);
    }
    __syncthreads();
    for (int c = t; c < 1024; c += 256) {           // L3 -> B
        int m = c >> 8, d = (c & 255) * 8;
        merge_chunk(A + 2 * m * 1024, 1024, A + 2 * m * 1024 + 1024, 1024,
                    B + m * 2048, d);
    }
    __syncthreads();
    for (int c = t; c < 1024; c += 256) {           // L4 -> A
        int m = c >> 9, d = (c & 511) * 8;
        merge_chunk(B + 2 * m * 2048, 2048, B + 2 * m * 2048 + 2048, 2048,
                    A + m * 4096, d);
    }
    __syncthreads();
    for (int c = t; c < NPRE / 8; c += 256)         // L5 -> B (top 6000)
        merge_chunk(A, 4096, A + 4096, 4096, B, c * 8);
    __syncthreads();
    for (int rank = t; rank < NPRE; rank += 256)
        decode_box(b, rank, B[rank], bbox, anchors);
    for (int i = t; i < NPRE; i += 256) supp[i] = 0;
    __syncthreads();
    const float4* boxes_b = g_boxes + b * NPRE;
    for (int i = 0; i < NPRE; ++i) {
        if (!supp[i]) {
            float4 bi_ = boxes_b[i];
            float ai = (bi_.z - bi_.x) * (bi_.w - bi_.y);
            for (int j = i + 1 + t; j < NPRE; j += 256) {
                if (supp[j]) continue;
                float4 c = boxes_b[j];
                float dy = fminf(bi_.z, c.z) - fmaxf(bi_.x, c.x);
                float dx = fminf(bi_.w, c.w) - fmaxf(bi_.y, c.y);
                if (dy > 0.f && dx > 0.f) {
                    float inter = dy * dx;
                    float ca = (c.z - c.x) * (c.w - c.y);
                    float uni = fmaxf(ai + ca - inter, 1e-12f);
                    if (__fdiv_rn(inter, uni) > NMS_THR) supp[j] = 1;
                }
            }
        }
        __syncthreads();
    }
    for (int k = t; k < NPROP * 4; k += 256) out[b * NPROP * 4 + k] = 0.f;
    if (t == 0) s_base = 0;
    __syncthreads();
    for (int tile = 0; tile < 24; ++tile) {
        int i = tile * 256 + t;
        int kp = (i < NPRE) ? (int)(1 - supp[i]) : 0;
        unsigned int m = __ballot_sync(0xffffffffu, kp);
        if (lane == 0) s_w[warp] = __popc(m);
        __syncthreads();
        int base = s_base;
        if (warp == 0 && lane < 8) {
            int wv = s_w[lane];
            for (int o = 1; o < 8; o <<= 1) {
                int u = __shfl_up_sync(0xffu, wv, o);
                if (lane >= o) wv += u;
            }
            s_w[lane] = wv;
        }
        __syncthreads();
        int prev = (warp == 0) ? 0 : s_w[warp - 1];
        int rank = base + prev + __popc(m & ((1u << lane) - 1u));
        if (kp && rank < NPROP)
            ((float4*)out)[b * NPROP + rank] = boxes_b[i];
        __syncthreads();
        if (t == 0) s_base = base + s_w[7];
        __syncthreads();
    }
}

// ---------------- launch ----------------
extern "C" void kernel_launch(void* const* d_in, const int* in_sizes, int n_in,
                              void* d_out, int out_size) {
    const float* probs   = (const float*)d_in[0];
    const float* bbox    = (const float*)d_in[1];
    const float* anchors = (const float*)d_in[2];
    float* out = (float*)d_out;

    const int fb_smem = 2 * CAND_FB * 8 + NPRE + 64;          // ~137 KB
    cudaFuncSetAttribute(fallback_kernel,
                         cudaFuncAttributeMaxDynamicSharedMemorySize, fb_smem);

    hist_kernel<<<512, 256>>>(probs);
    cutoff_kernel<<<BATCH, 1024>>>();
    compact_kernel<<<512, 256>>>(probs);
    sorttop_kernel<<<BATCH, 256>>>(bbox, anchors);
    edge_kernel<<<dim3(12, 24, BATCH), 64>>>();
    fixpoint_out_kernel<<<BATCH, 256>>>(out);
    fallback_kernel<<<BATCH, 256, fb_smem>>>(probs, bbox, anchors, out);  // no-op when done
}

// round 16
// speedup vs baseline: 1.6617x; 1.0224x over previous
#include <cuda_runtime.h>
#include <cstdint>
#include <math.h>

#define BATCH 8
#define NA 131072            // anchors per batch (2^17)
#define NPRE 6000            // PRE_NMS_LIMIT
#define NPROP 1000
#define CAND_FAST 2048       // fast-path candidate cap (fine bins: ~1536+~350)
#define CAND_FB 8192         // fallback candidate cap
#define HBINS 16384          // fine bins: (key>>15) - BIN_OFF, clamped
#define BIN_OFF 0x13F01      // (0xBF800000>>15) - (HBINS-1): score 1.0 -> bin 16383
#define NMS_THR 0.7f
#define N1 1536              // fast-path prefix rows
#define ECAP 6144            // edge list capacity per batch
#define PASSMAX 64

typedef unsigned long long u64;

// ---------------- device scratch (static, no allocation) ----------------
// Invariants: g_hist all-zero, g_cand_cnt/g_ecnt zero at entry of each launch
// (zero-init at load; each consumer kernel re-zeroes after use).
__device__ unsigned int  g_hist[BATCH * HBINS];
__device__ int           g_cutbin[BATCH];        // suffix >= N1 cut (fast)
__device__ int           g_cutbin6[BATCH];       // suffix >= NPRE cut (fallback)
__device__ int           g_cand_cnt[BATCH];
__device__ u64           g_cand[BATCH * CAND_FAST];
__device__ float4        g_boxes_tmp[BATCH * CAND_FAST];   // unsorted decoded boxes
__device__ float4        g_boxes[BATCH * NPRE];
__device__ int           g_ecnt[BATCH];
__device__ unsigned int  g_edges[BATCH * ECAP];
__device__ int           g_done[BATCH];

// ---------------- helpers ----------------
static __device__ __forceinline__ unsigned int score_key(float s) {
    unsigned int u = __float_as_uint(s);
    return u ^ ((unsigned int)((int)u >> 31) | 0x80000000u);
}
static __device__ __forceinline__ int key_bin(unsigned int key) {
    int b = (int)(key >> 15) - BIN_OFF;
    return b < 0 ? 0 : (b > HBINS - 1 ? HBINS - 1 : b);
}
static __device__ __forceinline__ int warp_alloc(bool pred, int* ctr) {
    unsigned int m = __ballot_sync(0xffffffffu, pred);
    int lane = threadIdx.x & 31;
    int leader = __ffs(m) - 1;
    int base = 0;
    if (m) {
        if (lane == leader) base = atomicAdd(ctr, __popc(m));
        base = __shfl_sync(0xffffffffu, base, leader);
    }
    return base + __popc(m & ((1u << lane) - 1u));
}
static __device__ __forceinline__ void cp_async16(unsigned int smem, const void* g) {
    asm volatile("cp.async.cg.shared.global [%0], [%1], 16;" :: "r"(smem), "l"(g) : "memory");
}
static __device__ __forceinline__ void cp_commit() {
    asm volatile("cp.async.commit_group;" ::: "memory");
}
static __device__ __forceinline__ void cp_wait0() {
    asm volatile("cp.async.wait_group 0;" ::: "memory");
}
// merge-path partition (DESC order): of first d outputs, how many come from A
static __device__ __forceinline__ int mpath(const u64* A, int lenA,
                                            const u64* B, int lenB, int d) {
    int lo = d - lenB; if (lo < 0) lo = 0;
    int hi = d < lenA ? d : lenA;
    while (lo < hi) {
        int mid = (lo + hi) >> 1;
        if (A[mid] > B[d - 1 - mid]) lo = mid + 1; else hi = mid;
    }
    return lo;
}
static __device__ __forceinline__ void merge_chunk(const u64* A, int lenA,
                                                   const u64* B, int lenB,
                                                   u64* out, int d) {
    int a = mpath(A, lenA, B, lenB, d);
    int bi = d - a;
#pragma unroll
    for (int r = 0; r < 8; ++r) {
        bool takeA = (a < lenA) && ((bi >= lenB) || (A[a] > B[bi]));
        out[d + r] = takeA ? A[a++] : B[bi++];
    }
}
// full box decode from anchor index (fallback path + compact pre-decode)
static __device__ __forceinline__ float4 compute_box(int b, unsigned int a,
                                                     const float* __restrict__ bbox,
                                                     const float* __restrict__ anchors) {
    size_t s4 = (((size_t)b << 17) + a) * 4;
    float d0 = bbox[s4 + 0] * 0.1f;
    float d1 = bbox[s4 + 1] * 0.1f;
    float d2 = bbox[s4 + 2] * 0.2f;
    float d3 = bbox[s4 + 3] * 0.2f;
    float a0 = anchors[s4 + 0], a1 = anchors[s4 + 1];
    float a2 = anchors[s4 + 2], a3 = anchors[s4 + 3];
    float h = a2 - a0, w = a3 - a1;
    float cy = a0 + 0.5f * h + d0 * h;
    float cx = a1 + 0.5f * w + d1 * w;
    float h2 = h * expf(d2);
    float w2 = w * expf(d3);
    float y1 = cy - 0.5f * h2;
    float x1 = cx - 0.5f * w2;
    float y2 = y1 + h2;
    float x2 = x1 + w2;
    y1 = fminf(fmaxf(y1, 0.f), 1.f);
    x1 = fminf(fmaxf(x1, 0.f), 1.f);
    y2 = fminf(fmaxf(y2, 0.f), 1.f);
    x2 = fminf(fmaxf(x2, 0.f), 1.f);
    return make_float4(y1, x1, y2, x2);
}

// ---------------- 1: histogram ----------------
__global__ void hist_kernel(const float* __restrict__ probs) {
    const float4* p4 = (const float4*)probs;
    int t = threadIdx.x;
    int base = blockIdx.x * 1024;
    int b = base >> 16;
    float4 x[4];
#pragma unroll
    for (int u = 0; u < 4; ++u) x[u] = p4[base + u * 256 + t];
    unsigned int* Hb = g_hist + (size_t)b * HBINS;
#pragma unroll
    for (int u = 0; u < 4; ++u) {
        atomicAdd(&Hb[key_bin(score_key(x[u].y))], 1u);
        atomicAdd(&Hb[key_bin(score_key(x[u].w))], 1u);
    }
}

// ---------------- 2: dual cutoff bins (self-cleaning hist) ----------------
__global__ void cutoff_kernel() {
    int b = blockIdx.x, t = threadIdx.x;            // 1024 threads, 16 bins each
    __shared__ unsigned int wtot[32];
    __shared__ unsigned int wsuf[32];
    uint4* H4 = (uint4*)(g_hist + (size_t)b * HBINS);
    int warp = t >> 5, lane = t & 31;
    uint4 h[4];
#pragma unroll
    for (int u = 0; u < 4; ++u) h[u] = H4[t * 4 + u];
    uint4 z = make_uint4(0u, 0u, 0u, 0u);
#pragma unroll
    for (int u = 0; u < 4; ++u) H4[t * 4 + u] = z;  // restore all-zero invariant
    unsigned int s = 0;
#pragma unroll
    for (int u = 0; u < 4; ++u) s += h[u].x + h[u].y + h[u].z + h[u].w;
    unsigned int ss = s;
#pragma unroll
    for (int o = 1; o < 32; o <<= 1) {
        unsigned int v = __shfl_down_sync(0xffffffffu, ss, o);
        if (lane + o < 32) ss += v;
    }
    if (lane == 0) wtot[warp] = ss;
    __syncthreads();
    if (warp == 0) {
        unsigned int wv = wtot[lane];
#pragma unroll
        for (int o = 1; o < 32; o <<= 1) {
            unsigned int v = __shfl_down_sync(0xffffffffu, wv, o);
            if (lane + o < 32) wv += v;
        }
        wsuf[lane] = wv;
    }
    __syncthreads();
    unsigned int after_warp = (warp < 31) ? wsuf[warp + 1] : 0u;
    unsigned int S = ss + after_warp;               // suffix from bin t*16
    unsigned int Snext = S - s;                     // suffix from bin (t+1)*16
    unsigned int bins[16];
#pragma unroll
    for (int u = 0; u < 4; ++u) {
        bins[u * 4 + 0] = h[u].x; bins[u * 4 + 1] = h[u].y;
        bins[u * 4 + 2] = h[u].z; bins[u * 4 + 3] = h[u].w;
    }
    if (S >= N1 && Snext < N1) {                    // fast cut (>= top-1536)
        unsigned int run = Snext;
        int cut = t * 16;
        for (int k = 15; k >= 0; --k) {
            run += bins[k];
            if (run >= N1) { cut = t * 16 + k; break; }
        }
        g_cutbin[b] = cut;
    }
    if (S >= NPRE && Snext < NPRE) {                // fallback cut (>= top-6000)
        unsigned int run = Snext;
        int cut = t * 16;
        for (int k = 15; k >= 0; --k) {
            run += bins[k];
            if (run >= NPRE) { cut = t * 16 + k; break; }
        }
        g_cutbin6[b] = cut;
    }
}

// ---------------- 3: compact fast candidates + pre-decode boxes ----------------
// Candidate word: [63:32]=key, [31:15]=(~a)&0x1FFFF (anchor asc tiebreak),
// [14:12]=0, [11:0]=slot. Slot bits never affect order ((key,anchor) unique).
__global__ void compact_kernel(const float* __restrict__ probs,
                               const float* __restrict__ bbox,
                               const float* __restrict__ anchors) {
    const float4* p4 = (const float4*)probs;
    int t = threadIdx.x;
    int base = blockIdx.x * 1024;
    int b = base >> 16;
    int cut = g_cutbin[b];
    float4 x[4];
#pragma unroll
    for (int u = 0; u < 4; ++u) x[u] = p4[base + u * 256 + t];
#pragma unroll
    for (int u = 0; u < 4; ++u) {
        int j = base + u * 256 + t;
        unsigned int k0 = score_key(x[u].y);
        unsigned int k1 = score_key(x[u].w);
        bool p0 = key_bin(k0) >= cut;
        bool p1 = key_bin(k1) >= cut;
        int pos0 = warp_alloc(p0, &g_cand_cnt[b]);
        if (p0 && pos0 < CAND_FAST) {
            unsigned int a = (unsigned int)((2 * j) & (NA - 1));
            g_cand[b * CAND_FAST + pos0] =
                ((u64)k0 << 32) | ((u64)((~a) & 0x1FFFFu) << 15) | (u64)pos0;
            g_boxes_tmp[b * CAND_FAST + pos0] = compute_box(b, a, bbox, anchors);
        }
        int pos1 = warp_alloc(p1, &g_cand_cnt[b]);
        if (p1 && pos1 < CAND_FAST) {
            unsigned int a = (unsigned int)((2 * j + 1) & (NA - 1));
            g_cand[b * CAND_FAST + pos1] =
                ((u64)k1 << 32) | ((u64)((~a) & 0x1FFFFu) << 15) | (u64)pos1;
            g_boxes_tmp[b * CAND_FAST + pos1] = compute_box(b, a, bbox, anchors);
        }
    }
}

// ---------------- warp-synchronous bitonic (8 elems/lane, i = lane*8 + r) ----------------
static __device__ __forceinline__ void shfl_stage(u64 v[8], int lane, int j, int k) {
    int jm = j >> 3;
#pragma unroll
    for (int r = 0; r < 8; ++r) {
        u64 other = __shfl_xor_sync(0xffffffffu, v[r], jm);
        int i = lane * 8 + r;
        bool lower = (lane & jm) == 0;
        bool desc = ((i & k) == 0);
        bool take_max = (lower == desc);
        u64 mx = v[r] > other ? v[r] : other;
        u64 mn = v[r] > other ? other : v[r];
        v[r] = take_max ? mx : mn;
    }
}
static __device__ __forceinline__ void reg_stage(u64 v[8], int lane, int j, int k) {
#pragma unroll
    for (int a = 0; a < 8; ++a) {
        if (!(a & j)) {
            int i = lane * 8 + a;
            bool desc = ((i & k) == 0);
            u64 x = v[a], y = v[a + j];
            if (desc ? (x < y) : (x > y)) { v[a] = y; v[a + j] = x; }
        }
    }
}
static __device__ __forceinline__ void warp_sort256(u64 v[8], int lane) {
    for (int k = 2; k <= 256; k <<= 1) {
        for (int j = k >> 1; j >= 8; j >>= 1) shfl_stage(v, lane, j, k);
        if (k > 4) reg_stage(v, lane, 4, k);
        if (k > 2) reg_stage(v, lane, 2, k);
        reg_stage(v, lane, 1, k);
    }
}

// ---------------- 4: sort(2048) -> top-N1 merge -> permute boxes (8 blocks, 256 thr) ----------------
__global__ void sorttop_kernel() {
    extern __shared__ u64 dsm[];                    // S[2048] + P[2048] + BX[2048 float4]
    u64* S = dsm;
    u64* P = dsm + CAND_FAST;
    float4* BX = (float4*)(dsm + 2 * CAND_FAST);
    int b = blockIdx.x, t = threadIdx.x;            // 256 threads = 8 warps
    int lane = t & 31, warp = t >> 5;
    int cnt = g_cand_cnt[b];
    int cw = cnt > CAND_FAST ? CAND_FAST : cnt;
    const u64* cand = g_cand + b * CAND_FAST;
    // prefetch the unsorted box table into smem while sorting (32 KB)
    {
        unsigned int sb = (unsigned int)__cvta_generic_to_shared(BX);
        const float4* src = g_boxes_tmp + b * CAND_FAST;
        for (int i = t; i < CAND_FAST; i += 256)
            cp_async16(sb + i * 16, src + i);
        cp_commit();
    }
    // 8 warps, 1 run each (8 runs of 256), register bitonic, no block sync
    {
        u64 v[8];
        int segbase = warp * 256;
#pragma unroll
        for (int r = 0; r < 8; ++r) {
            int i = segbase + lane * 8 + r;
            v[r] = (i < cw) ? cand[i] : 0ULL;
        }
        warp_sort256(v, lane);
#pragma unroll
        for (int r = 0; r < 8; ++r) S[segbase + lane * 8 + r] = v[r];
    }
    __syncthreads();
    // L1: 4 x (256,256) -> 512
    {
        int m = t >> 6, d = (t & 63) * 8;
        merge_chunk(S + 2 * m * 256, 256, S + 2 * m * 256 + 256, 256,
                    P + m * 512, d);
    }
    __syncthreads();
    // L2: 2 x (512,512) -> 1024
    {
        int m = t >> 7, d = (t & 127) * 8;
        merge_chunk(P + 2 * m * 512, 512, P + 2 * m * 512 + 512, 512,
                    S + m * 1024, d);
    }
    __syncthreads();
    // L3: (1024,1024) -> top N1
    if (t < N1 / 8)
        merge_chunk(S, 1024, S + 1024, 1024, P, t * 8);
    cp_wait0();
    __syncthreads();
    // permute: rank -> slot -> smem box -> coalesced g_boxes write
    for (int rank = t; rank < N1; rank += 256) {
        int slot = (int)(P[rank] & 0xFFFULL);
        g_boxes[b * NPRE + rank] = BX[slot];
    }
}

// ---------------- 5: edge emission over first N1 boxes ----------------
__global__ void edge_kernel() {
    int rowblk = blockIdx.x, colblk = blockIdx.y, b = blockIdx.z;
    if (colblk < 2 * rowblk) return;
    int t = threadIdx.x;
    int i0 = rowblk * 128 + t;
    int i1 = i0 + 64;
    __shared__ float4 s_box[64];
    __shared__ float  s_area[64];
    int jj0 = colblk * 64;
    const float4* boxes_b = g_boxes + b * NPRE;
    {
        float4 c = boxes_b[jj0 + t];
        s_box[t] = c;
        s_area[t] = (c.z - c.x) * (c.w - c.y);
    }
    __syncthreads();
    float4 rb0 = boxes_b[i0];
    float4 rb1 = boxes_b[i1];
    float ar0 = (rb0.z - rb0.x) * (rb0.w - rb0.y);
    float ar1 = (rb1.z - rb1.x) * (rb1.w - rb1.y);
#pragma unroll 4
    for (int j = 0; j < 64; ++j) {
        float4 c = s_box[j];
        float ca = s_area[j];
        int jj = jj0 + j;
        float dy0 = fminf(rb0.z, c.z) - fmaxf(rb0.x, c.x);
        float dx0 = fminf(rb0.w, c.w) - fmaxf(rb0.y, c.y);
        float dy1 = fminf(rb1.z, c.z) - fmaxf(rb1.x, c.x);
        float dx1 = fminf(rb1.w, c.w) - fmaxf(rb1.y, c.y);
        bool ov0 = (dy0 > 0.f) && (dx0 > 0.f) && (jj > i0);
        bool ov1 = (dy1 > 0.f) && (dx1 > 0.f) && (jj > i1);
        if (__any_sync(0xffffffffu, ov0 || ov1)) {
            bool e0 = false, e1 = false;
            if (ov0) {
                float inter = dy0 * dx0;
                float uni = fmaxf(ar0 + ca - inter, 1e-12f);
                e0 = __fdiv_rn(inter, uni) > NMS_THR;
            }
            if (ov1) {
                float inter = dy1 * dx1;
                float uni = fmaxf(ar1 + ca - inter, 1e-12f);
                e1 = __fdiv_rn(inter, uni) > NMS_THR;
            }
            int pos0 = warp_alloc(e0, &g_ecnt[b]);
            if (e0 && pos0 < ECAP)
                g_edges[b * ECAP + pos0] = ((unsigned int)i0 << 16) | (unsigned int)jj;
            int pos1 = warp_alloc(e1, &g_ecnt[b]);
            if (e1 && pos1 < ECAP)
                g_edges[b * ECAP + pos1] = ((unsigned int)i1 << 16) | (unsigned int)jj;
        }
    }
}

// ---------------- 6: fixpoint NMS on prefix + fused output write ----------------
__global__ void fixpoint_out_kernel(float* __restrict__ out) {
    int b = blockIdx.x, t = threadIdx.x;            // 256 threads
    int warp = t >> 5, lane = t & 31;
    __shared__ unsigned int  s_edges[ECAP];
    __shared__ unsigned char s_keep[N1];
    __shared__ unsigned char s_supp[N1];
    __shared__ int s_flag, s_total, s_base;
    __shared__ int s_w[8];
    int ec = g_ecnt[b];
    int cc = g_cand_cnt[b];
    if (t == 0) { g_ecnt[b] = 0; g_cand_cnt[b] = 0; }   // restore invariants
    if (ec > ECAP || cc > CAND_FAST) {                  // overflow -> exact fallback
        if (t == 0) g_done[b] = 0;
        return;
    }
    for (int i = t; i < ec; i += 256) s_edges[i] = g_edges[b * ECAP + i];
    for (int i = t; i < N1; i += 256) s_keep[i] = 1;
    __syncthreads();
    bool converged = false;
    for (int pass = 0; pass < PASSMAX; ++pass) {
        for (int i = t; i < N1; i += 256) s_supp[i] = 0;
        if (t == 0) s_flag = 0;
        __syncthreads();
        for (int e = t; e < ec; e += 256) {
            unsigned int p = s_edges[e];
            if (s_keep[p >> 16]) s_supp[p & 0xffffu] = 1;
        }
        __syncthreads();
        int ch = 0;
        for (int i = t; i < N1; i += 256) {
            unsigned char nk = (unsigned char)(1 - s_supp[i]);
            if (nk != s_keep[i]) { s_keep[i] = nk; ch = 1; }
        }
        if (ch) s_flag = 1;
        __syncthreads();
        if (!s_flag) { converged = true; break; }
    }
    if (t == 0) s_total = 0;
    __syncthreads();
    int cnt = 0;
    for (int i = t; i < N1; i += 256) cnt += s_keep[i];
    for (int off = 16; off > 0; off >>= 1) cnt += __shfl_down_sync(0xffffffffu, cnt, off);
    if (lane == 0) atomicAdd(&s_total, cnt);
    __syncthreads();
    int done = (converged && s_total >= NPROP) ? 1 : 0;
    if (t == 0) { g_done[b] = done; s_base = 0; }
    __syncthreads();
    if (!done) return;                              // fallback kernel writes output
    for (int k = t; k < NPROP * 4; k += 256) out[b * NPROP * 4 + k] = 0.f;
    __syncthreads();
    for (int tile = 0; tile < N1 / 256; ++tile) {
        int i = tile * 256 + t;
        int kp = (int)s_keep[i];
        unsigned int m = __ballot_sync(0xffffffffu, kp);
        if (lane == 0) s_w[warp] = __popc(m);
        __syncthreads();
        int base = s_base;
        if (warp == 0 && lane < 8) {
            int wv = s_w[lane];
            for (int o = 1; o < 8; o <<= 1) {
                int u = __shfl_up_sync(0xffu, wv, o);
                if (lane >= o) wv += u;
            }
            s_w[lane] = wv;                          // inclusive
        }
        __syncthreads();
        int prev = (warp == 0) ? 0 : s_w[warp - 1];
        int rank = base + prev + __popc(m & ((1u << lane) - 1u));
        if (kp && rank < NPROP)
            ((float4*)out)[b * NPROP + rank] = g_boxes[b * NPRE + i];
        __syncthreads();
        if (t == 0) s_base = base + s_w[7];
        __syncthreads();
    }
}

// ---------------- 7: FALLBACK all-in-one (guarded; ~never runs) ----------------
// Per batch: re-select with cutB -> full smem sort -> top-6000 decode ->
// sequential greedy NMS -> compact. Exact reference semantics.
__global__ void fallback_kernel(const float* __restrict__ probs,
                                const float* __restrict__ bbox,
                                const float* __restrict__ anchors,
                                float* __restrict__ out) {
    int b = blockIdx.x, t = threadIdx.x;            // 256 threads
    if (g_done[b]) return;
    extern __shared__ u64 fsm[];                    // A[8192] + B[8192] + supp + cnt
    u64* A = fsm;
    u64* B = fsm + CAND_FB;
    unsigned char* supp = (unsigned char*)(fsm + 2 * CAND_FB);
    int* s_cnt = (int*)(supp + NPRE + (8 - (NPRE & 7)));
    int warp = t >> 5, lane = t & 31;
    __shared__ int s_w[8];
    __shared__ int s_base;
    for (int i = t; i < CAND_FB; i += 256) A[i] = 0ULL;
    if (t == 0) *s_cnt = 0;
    __syncthreads();
    {
        int cut = g_cutbin6[b];
        const float4* p4 = (const float4*)probs + ((size_t)b << 16);
        for (int i = t; i < (NA / 2); i += 256) {
            float4 x = p4[i];
            unsigned int k0 = score_key(x.y);
            unsigned int k1 = score_key(x.w);
            bool p0 = key_bin(k0) >= cut;
            bool p1 = key_bin(k1) >= cut;
            int pos0 = warp_alloc(p0, s_cnt);
            if (p0 && pos0 < CAND_FB)
                A[pos0] = ((u64)k0 << 32) | (u64)(~(unsigned int)(2 * i));
            int pos1 = warp_alloc(p1, s_cnt);
            if (p1 && pos1 < CAND_FB)
                A[pos1] = ((u64)k1 << 32) | (u64)(~(unsigned int)(2 * i + 1));
        }
    }
    __syncthreads();
    for (int run = warp; run < 32; run += 8) {
        u64 v[8];
#pragma unroll
        for (int r = 0; r < 8; ++r) v[r] = A[run * 256 + lane * 8 + r];
        warp_sort256(v, lane);
#pragma unroll
        for (int r = 0; r < 8; ++r) A[run * 256 + lane * 8 + r] = v[r];
    }
    __syncthreads();
    for (int c = t; c < 1024; c += 256) {           // L1 -> B
        int m = c >> 6, d = (c & 63) * 8;
        merge_chunk(A + 2 * m * 256, 256, A + 2 * m * 256 + 256, 256, B + m * 512, d);
    }
    __syncthreads();
    for (int c = t; c < 1024; c += 256) {           // L2 -> A
        int m = c >> 7, d = (c & 127) * 8;
        merge_chunk(B + 2 * m * 512, 512, B + 2 * m * 512 + 512, 512, A + m * 1024, d);
    }
    __syncthreads();
    for (int c = t; c < 1024; c += 256) {           // L3 -> B
        int m = c >> 8, d = (c & 255) * 8;
        merge_chunk(A + 2 * m * 1024, 1024, A + 2 * m * 1024 + 1024, 1024,
                    B + m * 2048, d);
    }
    __syncthreads();
    for (int c = t; c < 1024; c += 256) {           // L4 -> A
        int m = c >> 9, d = (c & 511) * 8;
        merge_chunk(B + 2 * m * 2048, 2048, B + 2 * m * 2048 + 2048, 2048,
                    A + m * 4096, d);
    }
    __syncthreads();
    for (int c = t; c < NPRE / 8; c += 256)         // L5 -> B (top 6000)
        merge_chunk(A, 4096, A + 4096, 4096, B, c * 8);
    __syncthreads();
    for (int rank = t; rank < NPRE; rank += 256) {
        unsigned int a = ~(unsigned int)(B[rank] & 0xffffffffULL);
        g_boxes[b * NPRE + rank] = compute_box(b, a & (NA - 1), bbox, anchors);
    }
    for (int i = t; i < NPRE; i += 256) supp[i] = 0;
    __syncthreads();
    const float4* boxes_b = g_boxes + b * NPRE;
    for (int i = 0; i < NPRE; ++i) {
        if (!supp[i]) {
            float4 bi_ = boxes_b[i];
            float ai = (bi_.z - bi_.x) * (bi_.w - bi_.y);
            for (int j = i + 1 + t; j < NPRE; j += 256) {
                if (supp[j]) continue;
                float4 c = boxes_b[j];
                float dy = fminf(bi_.z, c.z) - fmaxf(bi_.x, c.x);
                float dx = fminf(bi_.w, c.w) - fmaxf(bi_.y, c.y);
                if (dy > 0.f && dx > 0.f) {
                    float inter = dy * dx;
                    float ca = (c.z - c.x) * (c.w - c.y);
                    float uni = fmaxf(ai + ca - inter, 1e-12f);
                    if (__fdiv_rn(inter, uni) > NMS_THR) supp[j] = 1;
                }
            }
        }
        __syncthreads();
    }
    for (int k = t; k < NPROP * 4; k += 256) out[b * NPROP * 4 + k] = 0.f;
    if (t == 0) s_base = 0;
    __syncthreads();
    for (int tile = 0; tile < 24; ++tile) {
        int i = tile * 256 + t;
        int kp = (i < NPRE) ? (int)(1 - supp[i]) : 0;
        unsigned int m = __ballot_sync(0xffffffffu, kp);
        if (lane == 0) s_w[warp] = __popc(m);
        __syncthreads();
        int base = s_base;
        if (warp == 0 && lane < 8) {
            int wv = s_w[lane];
            for (int o = 1; o < 8; o <<= 1) {
                int u = __shfl_up_sync(0xffu, wv, o);
                if (lane >= o) wv += u;
            }
            s_w[lane] = wv;
        }
        __syncthreads();
        int prev = (warp == 0) ? 0 : s_w[warp - 1];
        int rank = base + prev + __popc(m & ((1u << lane) - 1u));
        if (kp && rank < NPROP)
            ((float4*)out)[b * NPROP + rank] = boxes_b[i];
        __syncthreads();
        if (t == 0) s_base = base + s_w[7];
        __syncthreads();
    }
}

// ---------------- launch ----------------
extern "C" void kernel_launch(void* const* d_in, const int* in_sizes, int n_in,
                              void* d_out, int out_size) {
    const float* probs   = (const float*)d_in[0];
    const float* bbox    = (const float*)d_in[1];
    const float* anchors = (const float*)d_in[2];
    float* out = (float*)d_out;

    const int st_smem = 2 * CAND_FAST * 8 + CAND_FAST * 16;   // 65536 B
    const int fb_smem = 2 * CAND_FB * 8 + NPRE + 64;          // ~137 KB
    cudaFuncSetAttribute(sorttop_kernel,
                         cudaFuncAttributeMaxDynamicSharedMemorySize, st_smem);
    cudaFuncSetAttribute(fallback_kernel,
                         cudaFuncAttributeMaxDynamicSharedMemorySize, fb_smem);

    hist_kernel<<<512, 256>>>(probs);
    cutoff_kernel<<<BATCH, 1024>>>();
    compact_kernel<<<512, 256>>>(probs, bbox, anchors);
    sorttop_kernel<<<BATCH, 256, st_smem>>>();
    edge_kernel<<<dim3(12, 24, BATCH), 64>>>();
    fixpoint_out_kernel<<<BATCH, 256>>>(out);
    fallback_kernel<<<BATCH, 256, fb_smem>>>(probs, bbox, anchors, out);  // no-op when done
}